// round 5
// baseline (speedup 1.0000x reference)
#include <cuda_runtime.h>
#include <stdint.h>
#include <math.h>

#define BB 32
#define SS 2048
#define DD 128
#define BQ 128
#define BK 64
#define NITER (SS / BK)
#define NTH 256

// ===========================================================================
// Dropout mask (partitionable threefry, verified bit-exact in R2)
// ===========================================================================
__device__ uint32_t g_mask[1u << 22];   // 2^27 bits

__device__ __forceinline__ uint32_t rotl32(uint32_t x, int r) {
    return __funnelshift_l(x, x, r);
}
#define TF_ROUND(r) do { x0 += x1; x1 = rotl32(x1, (r)); x1 ^= x0; } while (0)
__device__ __forceinline__ uint32_t threefry_fold_0_42(uint32_t c0, uint32_t c1) {
    const uint32_t ks0 = 0u, ks1 = 42u, ks2 = 42u ^ 0x1BD11BDAu;
    uint32_t x0 = c0 + ks0, x1 = c1 + ks1;
    TF_ROUND(13); TF_ROUND(15); TF_ROUND(26); TF_ROUND(6);
    x0 += ks1; x1 += ks2 + 1u;
    TF_ROUND(17); TF_ROUND(29); TF_ROUND(16); TF_ROUND(24);
    x0 += ks2; x1 += ks0 + 2u;
    TF_ROUND(13); TF_ROUND(15); TF_ROUND(26); TF_ROUND(6);
    x0 += ks0; x1 += ks1 + 3u;
    TF_ROUND(17); TF_ROUND(29); TF_ROUND(16); TF_ROUND(24);
    x0 += ks1; x1 += ks2 + 4u;
    TF_ROUND(13); TF_ROUND(15); TF_ROUND(26); TF_ROUND(6);
    x0 += ks2; x1 += ks0 + 5u;
    return x0 ^ x1;
}
__global__ void __launch_bounds__(NTH) mask_kernel() {
    const uint32_t TH = 3006477312u;              // 5872026 << 9
    uint32_t t = blockIdx.x * NTH + threadIdx.x;
    uint32_t base = t << 5;
    uint32_t w = 0u;
#pragma unroll 8
    for (int j = 0; j < 32; j++) {
        uint32_t bits = threefry_fold_0_42(0u, base + (uint32_t)j);
        w |= (bits < TH) ? (1u << j) : 0u;
    }
    g_mask[t] = w;
}

// ===========================================================================
// mma.sync tf32 helpers
// ===========================================================================
__device__ __forceinline__ void mma_tf32(float* c, const uint32_t* a,
                                         uint32_t b0, uint32_t b1) {
    asm volatile(
        "mma.sync.aligned.m16n8k8.row.col.f32.tf32.tf32.f32 "
        "{%0,%1,%2,%3}, {%4,%5,%6,%7}, {%8,%9}, {%0,%1,%2,%3};"
        : "+f"(c[0]), "+f"(c[1]), "+f"(c[2]), "+f"(c[3])
        : "r"(a[0]), "r"(a[1]), "r"(a[2]), "r"(a[3]), "r"(b0), "r"(b1));
}
__device__ __forceinline__ uint32_t tf32_rna(float x) {
    uint32_t u;
    asm("cvt.rna.tf32.f32 %0, %1;" : "=r"(u) : "f"(x));
    return u;
}
// split: hi = truncate-to-tf32, lo = truncate(x - hi)
__device__ __forceinline__ void split_tf32(float x, uint32_t& h, uint32_t& l) {
    uint32_t u = __float_as_uint(x);
    h = u & 0xffffe000u;
    float r = x - __uint_as_float(h);
    l = __float_as_uint(r) & 0xffffe000u;
}
__device__ __forceinline__ uint32_t smem_u32(const void* p) {
    uint32_t a;
    asm("{ .reg .u64 t; cvta.to.shared.u64 t, %1; cvt.u32.u64 %0, t; }"
        : "=r"(a) : "l"(p));
    return a;
}
__device__ __forceinline__ void cp16(uint32_t saddr, const void* g) {
    asm volatile("cp.async.cg.shared.global [%0], [%1], 16;"
                 :: "r"(saddr), "l"(g) : "memory");
}
#define CP_COMMIT() asm volatile("cp.async.commit_group;" ::: "memory")
#define CP_WAIT(n)  asm volatile("cp.async.wait_group %0;" :: "n"(n) : "memory")

// smem layout (floats / bytes)
#define QSTR 132                 // Q row stride (floats)  -> bank step 4
#define KSTR 132                 // K row stride (floats)
#define VSTR 136                 // V row stride (floats)  -> bank step 8
#define KBUF (64 * KSTR * 4)     // 33792 B per K buffer
#define VBUF (64 * VSTR * 4)     // 34816 B per V buffer
#define OFF_Q 0
#define OFF_K (128 * QSTR * 4)   // 67584
#define OFF_V (OFF_K + 2 * KBUF) // 135168
#define SMEM_BYTES (OFF_V + 2 * VBUF)  // 204800

__global__ void __launch_bounds__(NTH) attn_mma(
    const float* __restrict__ q, const float* __restrict__ k,
    const float* __restrict__ v, const float* __restrict__ scale,
    float* __restrict__ out) {
    extern __shared__ char smem_raw[];
    float* Qs = (float*)(smem_raw + OFF_Q);     // [128][132] fp32 (scaled)
    const uint32_t sb = smem_u32(smem_raw);
    const uint32_t sbK = sb + OFF_K;
    const uint32_t sbV = sb + OFF_V;

    const int tid = threadIdx.x;
    const int lane = tid & 31;
    const int w = tid >> 5;
    const int g = lane >> 2;        // groupID
    const int tig = lane & 3;       // threadID in group
    const int wrow = w * 16;
    const int b = blockIdx.y;
    const int q0 = blockIdx.x * BQ;

    const float* kb = k + (size_t)b * SS * DD;
    const float* vb = v + (size_t)b * SS * DD;

    const int ldrow = tid >> 5;     // loader row (0..63 over 8 iters)
    const int ldc4 = (tid & 31) * 4;

    // ---- issue cp.async for tile 0 ----
    {
        const float* kt = kb;
        const float* vt = vb;
#pragma unroll
        for (int i = 0; i < 8; i++) {
            int row = ldrow + i * 8;
            cp16(sbK + (uint32_t)(row * KSTR + ldc4) * 4u, kt + row * DD + ldc4);
            cp16(sbV + (uint32_t)(row * VSTR + ldc4) * 4u, vt + row * DD + ldc4);
        }
    }
    CP_COMMIT();

    // ---- load Q tile (scaled fp32) into smem (overlaps cp.async) ----
    {
        const float sc = scale[b];
        const float* qb = q + ((size_t)b * SS + q0) * DD;
#pragma unroll
        for (int i = 0; i < 16; i++) {
            int f = tid + i * NTH;          // 4096 float4
            int row = f >> 5, c4 = f & 31;
            float4 x = *(const float4*)(qb + row * DD + c4 * 4);
            float4 y = make_float4(x.x * sc, x.y * sc, x.z * sc, x.w * sc);
            *(float4*)(Qs + row * QSTR + c4 * 4) = y;
        }
    }

    const int r0 = wrow + g;
    const int r1 = wrow + g + 8;
    const int gi0 = q0 + r0;
    const int gi1 = q0 + r1;
    const uint32_t mbase0 = (((uint32_t)b << 11) + (uint32_t)gi0) << 6;
    const uint32_t mbase1 = (((uint32_t)b << 11) + (uint32_t)gi1) << 6;
    const float L2E = 1.4426950408889634f;
    const int srcA = (lane & 28) | (tig >> 1);
    const int srcB = srcA | 2;
    const uint32_t FM = 0xffffffffu;

    float m0 = -INFINITY, m1 = -INFINITY, l0 = 0.f, l1 = 0.f;
    float O[16][4];
#pragma unroll
    for (int nt = 0; nt < 16; nt++)
#pragma unroll
        for (int e = 0; e < 4; e++) O[nt][e] = 0.f;

    for (int t = 0; t < NITER; t++) {
        const int buf = t & 1;
        // ---- prefetch tile t+1 into the other buffer ----
        if (t + 1 < NITER) {
            const float* kt = kb + (size_t)(t + 1) * BK * DD;
            const float* vt = vb + (size_t)(t + 1) * BK * DD;
            const uint32_t kd = sbK + (uint32_t)(buf ^ 1) * KBUF;
            const uint32_t vd = sbV + (uint32_t)(buf ^ 1) * VBUF;
#pragma unroll
            for (int i = 0; i < 8; i++) {
                int row = ldrow + i * 8;
                cp16(kd + (uint32_t)(row * KSTR + ldc4) * 4u, kt + row * DD + ldc4);
                cp16(vd + (uint32_t)(row * VSTR + ldc4) * 4u, vt + row * DD + ldc4);
            }
            CP_COMMIT();
            CP_WAIT(1);
        } else {
            CP_WAIT(0);
        }
        __syncthreads();

        const float* Kb = (const float*)(smem_raw + OFF_K + buf * KBUF);
        const uint32_t* Vb = (const uint32_t*)(smem_raw + OFF_V + buf * VBUF);

        // ---- gemm1: S[16,64] = Q K^T, 3-pass tf32 split, K split on the fly ----
        float S[8][4];
#pragma unroll
        for (int nt = 0; nt < 8; nt++)
#pragma unroll
            for (int e = 0; e < 4; e++) S[nt][e] = 0.f;

#pragma unroll 1
        for (int ks = 0; ks < 16; ks++) {
            const int kc = ks * 8 + tig;
            uint32_t ah[4], al[4];
            split_tf32(Qs[r0 * QSTR + kc], ah[0], al[0]);
            split_tf32(Qs[r1 * QSTR + kc], ah[1], al[1]);
            split_tf32(Qs[r0 * QSTR + kc + 4], ah[2], al[2]);
            split_tf32(Qs[r1 * QSTR + kc + 4], ah[3], al[3]);
            float kf0[8], kf1[8];
#pragma unroll
            for (int nt = 0; nt < 8; nt++) {
                kf0[nt] = Kb[(nt * 8 + g) * KSTR + kc];
                kf1[nt] = Kb[(nt * 8 + g) * KSTR + kc + 4];
            }
#pragma unroll
            for (int nt = 0; nt < 8; nt++) {
                uint32_t kh0, kl0, kh1, kl1;
                split_tf32(kf0[nt], kh0, kl0);
                split_tf32(kf1[nt], kh1, kl1);
                mma_tf32(S[nt], ah, kh0, kh1);
                mma_tf32(S[nt], ah, kl0, kl1);
                mma_tf32(S[nt], al, kh0, kh1);
            }
        }

        // ---- online softmax + dropout + in-register P transpose ----
        uint2 mwa = *(const uint2*)(g_mask + mbase0 + 2u * (uint32_t)t);
        uint2 mwb = *(const uint2*)(g_mask + mbase1 + 2u * (uint32_t)t);
        uint64_t mm0 = (uint64_t)mwa.x | ((uint64_t)mwa.y << 32);
        uint64_t mm1 = (uint64_t)mwb.x | ((uint64_t)mwb.y << 32);

        float rmax0 = -INFINITY, rmax1 = -INFINITY;
#pragma unroll
        for (int nt = 0; nt < 8; nt++) {
            rmax0 = fmaxf(rmax0, fmaxf(S[nt][0], S[nt][1]));
            rmax1 = fmaxf(rmax1, fmaxf(S[nt][2], S[nt][3]));
        }
        rmax0 = fmaxf(rmax0, __shfl_xor_sync(FM, rmax0, 1));
        rmax0 = fmaxf(rmax0, __shfl_xor_sync(FM, rmax0, 2));
        rmax1 = fmaxf(rmax1, __shfl_xor_sync(FM, rmax1, 1));
        rmax1 = fmaxf(rmax1, __shfl_xor_sync(FM, rmax1, 2));
        float mn0 = fmaxf(m0, rmax0), mn1 = fmaxf(m1, rmax1);
        float fr0 = exp2f((m0 - mn0) * L2E);
        float fr1 = exp2f((m1 - mn1) * L2E);

        uint32_t PA[8][4];
        float rs0 = 0.f, rs1 = 0.f;
#pragma unroll
        for (int nt = 0; nt < 8; nt++) {
            const int c = nt * 8 + 2 * tig;
            float e00 = exp2f((S[nt][0] - mn0) * L2E);
            float e01 = exp2f((S[nt][1] - mn0) * L2E);
            float e10 = exp2f((S[nt][2] - mn1) * L2E);
            float e11 = exp2f((S[nt][3] - mn1) * L2E);
            rs0 += e00 + e01;
            rs1 += e10 + e11;
            uint32_t p00 = ((mm0 >> c) & 1u) ? tf32_rna(e00) : 0u;
            uint32_t p01 = ((mm0 >> (c + 1)) & 1u) ? tf32_rna(e01) : 0u;
            uint32_t p10 = ((mm1 >> c) & 1u) ? tf32_rna(e10) : 0u;
            uint32_t p11 = ((mm1 >> (c + 1)) & 1u) ? tf32_rna(e11) : 0u;
            // quad transpose: build gemm2 A-fragment for k-slice nt
            uint32_t t0, t1;
            t0 = __shfl_sync(FM, p00, srcA); t1 = __shfl_sync(FM, p01, srcA);
            PA[nt][0] = (tig & 1) ? t1 : t0;
            t0 = __shfl_sync(FM, p10, srcA); t1 = __shfl_sync(FM, p11, srcA);
            PA[nt][1] = (tig & 1) ? t1 : t0;
            t0 = __shfl_sync(FM, p00, srcB); t1 = __shfl_sync(FM, p01, srcB);
            PA[nt][2] = (tig & 1) ? t1 : t0;
            t0 = __shfl_sync(FM, p10, srcB); t1 = __shfl_sync(FM, p11, srcB);
            PA[nt][3] = (tig & 1) ? t1 : t0;
        }
        rs0 += __shfl_xor_sync(FM, rs0, 1);
        rs0 += __shfl_xor_sync(FM, rs0, 2);
        rs1 += __shfl_xor_sync(FM, rs1, 1);
        rs1 += __shfl_xor_sync(FM, rs1, 2);
        l0 = l0 * fr0 + rs0; m0 = mn0;
        l1 = l1 * fr1 + rs1; m1 = mn1;

        // rescale O
#pragma unroll
        for (int nt = 0; nt < 16; nt++) {
            O[nt][0] *= fr0; O[nt][1] *= fr0;
            O[nt][2] *= fr1; O[nt][3] *= fr1;
        }

        // ---- gemm2: O += P V  (V rounded to tf32 at use: bits + 0x1000) ----
#pragma unroll 1
        for (int ks = 0; ks < 8; ks++) {
            const int kr0 = (ks * 8 + tig) * VSTR;
            const int kr1 = (ks * 8 + tig + 4) * VSTR;
            uint32_t vb0[16], vb1[16];
#pragma unroll
            for (int nt = 0; nt < 16; nt++) {
                vb0[nt] = Vb[kr0 + nt * 8 + g] + 0x1000u;
                vb1[nt] = Vb[kr1 + nt * 8 + g] + 0x1000u;
            }
#pragma unroll
            for (int nt = 0; nt < 16; nt++)
                mma_tf32(O[nt], PA[ks], vb0[nt], vb1[nt]);
        }
        __syncthreads();   // done reading buf before cp.async overwrites it
    }

    // ---- epilogue ----
    const float inv0 = 1.f / (l0 * 0.7f);
    const float inv1 = 1.f / (l1 * 0.7f);
    float* o0 = out + ((size_t)b * SS + gi0) * DD;
    float* o1 = out + ((size_t)b * SS + gi1) * DD;
#pragma unroll
    for (int nt = 0; nt < 16; nt++) {
        const int c = nt * 8 + 2 * tig;
        *(float2*)(o0 + c) = make_float2(O[nt][0] * inv0, O[nt][1] * inv0);
        *(float2*)(o1 + c) = make_float2(O[nt][2] * inv1, O[nt][3] * inv1);
    }
}

// ---------------------------------------------------------------------------
extern "C" void kernel_launch(void* const* d_in, const int* in_sizes, int n_in,
                              void* d_out, int out_size) {
    (void)in_sizes; (void)n_in; (void)out_size;
    const float* q = (const float*)d_in[0];
    const float* k = (const float*)d_in[1];
    const float* v = (const float*)d_in[2];
    const float* scale = (const float*)d_in[3];
    float* out = (float*)d_out;

    static const bool _init = []() {
        cudaFuncSetAttribute(attn_mma,
                             cudaFuncAttributeMaxDynamicSharedMemorySize,
                             SMEM_BYTES);
        return true;
    }();
    (void)_init;

    mask_kernel<<<(1 << 22) / NTH, NTH>>>();
    dim3 grid(SS / BQ, BB);
    attn_mma<<<grid, NTH, SMEM_BYTES>>>(q, k, v, scale, out);
}

// round 7
// speedup vs baseline: 1.1529x; 1.1529x over previous
#include <cuda_runtime.h>
#include <stdint.h>
#include <math.h>

#define BB 32
#define SS 2048
#define DD 128
#define BQ 128
#define BK 64
#define NITER (SS / BK)
#define NTH 512
#define MTH 256

// ===========================================================================
// Dropout mask (partitionable threefry, verified bit-exact in R2)
// ===========================================================================
__device__ uint32_t g_mask[1u << 22];   // 2^27 bits

__device__ __forceinline__ uint32_t rotl32(uint32_t x, int r) {
    return __funnelshift_l(x, x, r);
}
#define TF_ROUND(r) do { x0 += x1; x1 = rotl32(x1, (r)); x1 ^= x0; } while (0)
__device__ __forceinline__ uint32_t threefry_fold_0_42(uint32_t c0, uint32_t c1) {
    const uint32_t ks0 = 0u, ks1 = 42u, ks2 = 42u ^ 0x1BD11BDAu;
    uint32_t x0 = c0 + ks0, x1 = c1 + ks1;
    TF_ROUND(13); TF_ROUND(15); TF_ROUND(26); TF_ROUND(6);
    x0 += ks1; x1 += ks2 + 1u;
    TF_ROUND(17); TF_ROUND(29); TF_ROUND(16); TF_ROUND(24);
    x0 += ks2; x1 += ks0 + 2u;
    TF_ROUND(13); TF_ROUND(15); TF_ROUND(26); TF_ROUND(6);
    x0 += ks0; x1 += ks1 + 3u;
    TF_ROUND(17); TF_ROUND(29); TF_ROUND(16); TF_ROUND(24);
    x0 += ks1; x1 += ks2 + 4u;
    TF_ROUND(13); TF_ROUND(15); TF_ROUND(26); TF_ROUND(6);
    x0 += ks2; x1 += ks0 + 5u;
    return x0 ^ x1;
}
__global__ void __launch_bounds__(MTH) mask_kernel() {
    const uint32_t TH = 3006477312u;              // 5872026 << 9
    uint32_t t = blockIdx.x * MTH + threadIdx.x;
    uint32_t base = t << 5;
    uint32_t w = 0u;
#pragma unroll 8
    for (int j = 0; j < 32; j++) {
        uint32_t bits = threefry_fold_0_42(0u, base + (uint32_t)j);
        w |= (bits < TH) ? (1u << j) : 0u;
    }
    g_mask[t] = w;
}

// ===========================================================================
// mma.sync tf32 helpers
// ===========================================================================
__device__ __forceinline__ void mma_tf32(float* c, const uint32_t* a,
                                         uint32_t b0, uint32_t b1) {
    asm volatile(
        "mma.sync.aligned.m16n8k8.row.col.f32.tf32.tf32.f32 "
        "{%0,%1,%2,%3}, {%4,%5,%6,%7}, {%8,%9}, {%0,%1,%2,%3};"
        : "+f"(c[0]), "+f"(c[1]), "+f"(c[2]), "+f"(c[3])
        : "r"(a[0]), "r"(a[1]), "r"(a[2]), "r"(a[3]), "r"(b0), "r"(b1));
}
__device__ __forceinline__ uint32_t tf32_rna(float x) {
    uint32_t u;
    asm("cvt.rna.tf32.f32 %0, %1;" : "=r"(u) : "f"(x));
    return u;
}
__device__ __forceinline__ void split_tf32(float x, uint32_t& h, uint32_t& l) {
    uint32_t u = __float_as_uint(x);
    h = u & 0xffffe000u;
    float r = x - __uint_as_float(h);
    l = __float_as_uint(r) & 0xffffe000u;
}
__device__ __forceinline__ uint32_t smem_u32(const void* p) {
    uint32_t a;
    asm("{ .reg .u64 t; cvta.to.shared.u64 t, %1; cvt.u32.u64 %0, t; }"
        : "=r"(a) : "l"(p));
    return a;
}
__device__ __forceinline__ void cp16(uint32_t saddr, const void* g) {
    asm volatile("cp.async.cg.shared.global [%0], [%1], 16;"
                 :: "r"(saddr), "l"(g) : "memory");
}
#define CP_COMMIT() asm volatile("cp.async.commit_group;" ::: "memory")
#define CP_WAIT(n)  asm volatile("cp.async.wait_group %0;" :: "n"(n) : "memory")

// smem layout
#define QSTR 132
#define KSTR 132
#define VSTR 136
#define PSTR 68
#define KBUF (64 * KSTR * 4)          // 33792
#define VBUF (64 * VSTR * 4)          // 34816
#define OFF_Q 0
#define OFF_K (128 * QSTR * 4)        // 67584
#define OFF_V (OFF_K + 2 * KBUF)      // 135168
#define OFF_P (OFF_V + VBUF)          // 169984
#define OFF_MX (OFF_P + 128 * PSTR * 4)   // 204800  pmax [2][128]
#define OFF_SM (OFF_MX + 1024)        // 205824  psum [2][128]
#define SMEM_BYTES (OFF_SM + 1024)    // 206848

__global__ void __launch_bounds__(NTH) attn_mma(
    const float* __restrict__ q, const float* __restrict__ k,
    const float* __restrict__ v, const float* __restrict__ scale,
    float* __restrict__ out) {
    extern __shared__ char smem_raw[];
    float* Qs = (float*)(smem_raw + OFF_Q);           // [128][132] scaled fp32
    uint32_t* Ps = (uint32_t*)(smem_raw + OFF_P);     // [128][68] tf32 masked P
    float* PMX = (float*)(smem_raw + OFF_MX);         // [2][128]
    float* PSM = (float*)(smem_raw + OFF_SM);         // [2][128]
    const uint32_t sb = smem_u32(smem_raw);
    const uint32_t sbK = sb + OFF_K;
    const uint32_t sbV = sb + OFF_V;

    const int tid = threadIdx.x;
    const int lane = tid & 31;
    const int w = tid >> 5;           // 0..15
    const int rb = w >> 1;            // row block 0..7
    const int ch = w & 1;             // column half
    const int g = lane >> 2;
    const int tig = lane & 3;
    const int wrow = rb * 16;
    const int b = blockIdx.y;
    const int q0 = blockIdx.x * BQ;

    const float* kb = k + (size_t)b * SS * DD;
    const float* vb = v + (size_t)b * SS * DD;

    const int ldrow = tid >> 5;       // 0..15 ; 4 iters cover 64 rows
    const int ldc4 = (tid & 31) * 4;

    // ---- preload tile 0: group A0 = {K0}, group B0 = {V0} ----
#pragma unroll
    for (int i = 0; i < 4; i++) {
        int row = ldrow + i * 16;
        cp16(sbK + (uint32_t)(row * KSTR + ldc4) * 4u, kb + row * DD + ldc4);
    }
    CP_COMMIT();
#pragma unroll
    for (int i = 0; i < 4; i++) {
        int row = ldrow + i * 16;
        cp16(sbV + (uint32_t)(row * VSTR + ldc4) * 4u, vb + row * DD + ldc4);
    }
    CP_COMMIT();

    // ---- load Q tile (scaled fp32) into smem (overlaps cp.async) ----
    {
        const float sc = scale[b];
        const float* qb = q + ((size_t)b * SS + q0) * DD;
#pragma unroll
        for (int i = 0; i < 8; i++) {
            int f = tid + i * NTH;          // 4096 float4
            int row = f >> 5, c4 = f & 31;
            float4 x = *(const float4*)(qb + row * DD + c4 * 4);
            float4 y = make_float4(x.x * sc, x.y * sc, x.z * sc, x.w * sc);
            *(float4*)(Qs + row * QSTR + c4 * 4) = y;
        }
    }

    const int r0 = wrow + g;
    const int r1 = wrow + g + 8;
    const int gi0 = q0 + r0;
    const int gi1 = q0 + r1;
    const uint32_t mbase0 = ((((uint32_t)b << 11) + (uint32_t)gi0) << 6) + (uint32_t)ch;
    const uint32_t mbase1 = ((((uint32_t)b << 11) + (uint32_t)gi1) << 6) + (uint32_t)ch;
    const float L2E = 1.4426950408889634f;
    const uint32_t FM = 0xffffffffu;

    float m0 = -INFINITY, m1 = -INFINITY, l0 = 0.f, l1 = 0.f;
    float O[8][4];
#pragma unroll
    for (int nt = 0; nt < 8; nt++)
#pragma unroll
        for (int e = 0; e < 4; e++) O[nt][e] = 0.f;

    for (int t = 0; t < NITER; t++) {
        const int buf = t & 1;
        // ---- group A(t+1): prefetch K(t+1) into the other K buffer ----
        if (t + 1 < NITER) {
            const float* kt = kb + (size_t)(t + 1) * BK * DD;
            const uint32_t kd = sbK + (uint32_t)(buf ^ 1) * KBUF;
#pragma unroll
            for (int i = 0; i < 4; i++) {
                int row = ldrow + i * 16;
                cp16(kd + (uint32_t)(row * KSTR + ldc4) * 4u, kt + row * DD + ldc4);
            }
        }
        CP_COMMIT();
        // pending: {B(t)=V(t), A(t+1)} after this wait → K(t) ready
        CP_WAIT(2);
        __syncthreads();   // sync1: K(t) visible; gemm2(t-1) done

        const float* Kb = (const float*)(smem_raw + OFF_K + buf * KBUF);

        // ---- gemm1: S[16 rows][32 cols of ch] = Q K^T, 3-pass tf32 ----
        float S[4][4];
#pragma unroll
        for (int nt = 0; nt < 4; nt++)
#pragma unroll
            for (int e = 0; e < 4; e++) S[nt][e] = 0.f;

#pragma unroll 1
        for (int ks = 0; ks < 16; ks++) {
            const int kc = ks * 8 + tig;
            uint32_t ah[4], al[4];
            split_tf32(Qs[r0 * QSTR + kc], ah[0], al[0]);
            split_tf32(Qs[r1 * QSTR + kc], ah[1], al[1]);
            split_tf32(Qs[r0 * QSTR + kc + 4], ah[2], al[2]);
            split_tf32(Qs[r1 * QSTR + kc + 4], ah[3], al[3]);
#pragma unroll
            for (int nt = 0; nt < 4; nt++) {
                const int j = ch * 32 + nt * 8 + g;
                float kf0 = Kb[j * KSTR + kc];
                float kf1 = Kb[j * KSTR + kc + 4];
                uint32_t kh0, kl0, kh1, kl1;
                split_tf32(kf0, kh0, kl0);
                split_tf32(kf1, kh1, kl1);
                mma_tf32(S[nt], ah, kh0, kh1);
                mma_tf32(S[nt], ah, kl0, kl1);
                mma_tf32(S[nt], al, kh0, kh1);
            }
        }

        // ---- softmax phase 1: partial row max over this warp's 32 cols ----
        float rmax0 = -INFINITY, rmax1 = -INFINITY;
#pragma unroll
        for (int nt = 0; nt < 4; nt++) {
            rmax0 = fmaxf(rmax0, fmaxf(S[nt][0], S[nt][1]));
            rmax1 = fmaxf(rmax1, fmaxf(S[nt][2], S[nt][3]));
        }
        rmax0 = fmaxf(rmax0, __shfl_xor_sync(FM, rmax0, 1));
        rmax0 = fmaxf(rmax0, __shfl_xor_sync(FM, rmax0, 2));
        rmax1 = fmaxf(rmax1, __shfl_xor_sync(FM, rmax1, 1));
        rmax1 = fmaxf(rmax1, __shfl_xor_sync(FM, rmax1, 2));
        PMX[ch * 128 + r0] = rmax0;
        PMX[ch * 128 + r1] = rmax1;
        __syncthreads();   // sync2: partial maxima visible

        const float mn0 = fmaxf(m0, fmaxf(PMX[r0], PMX[128 + r0]));
        const float mn1 = fmaxf(m1, fmaxf(PMX[r1], PMX[128 + r1]));
        const float fr0 = exp2f((m0 - mn0) * L2E);
        const float fr1 = exp2f((m1 - mn1) * L2E);

        const uint32_t mw0 = g_mask[mbase0 + 2u * (uint32_t)t];
        const uint32_t mw1 = g_mask[mbase1 + 2u * (uint32_t)t];

        float rs0 = 0.f, rs1 = 0.f;
#pragma unroll
        for (int nt = 0; nt < 4; nt++) {
            const int c = nt * 8 + 2 * tig;     // local col in this 32-col half
            float e00 = exp2f((S[nt][0] - mn0) * L2E);
            float e01 = exp2f((S[nt][1] - mn0) * L2E);
            float e10 = exp2f((S[nt][2] - mn1) * L2E);
            float e11 = exp2f((S[nt][3] - mn1) * L2E);
            rs0 += e00 + e01;
            rs1 += e10 + e11;
            uint2 p0, p1;
            p0.x = ((mw0 >> c) & 1u) ? tf32_rna(e00) : 0u;
            p0.y = ((mw0 >> (c + 1)) & 1u) ? tf32_rna(e01) : 0u;
            p1.x = ((mw1 >> c) & 1u) ? tf32_rna(e10) : 0u;
            p1.y = ((mw1 >> (c + 1)) & 1u) ? tf32_rna(e11) : 0u;
            *(uint2*)(Ps + r0 * PSTR + ch * 32 + c) = p0;
            *(uint2*)(Ps + r1 * PSTR + ch * 32 + c) = p1;
        }
        rs0 += __shfl_xor_sync(FM, rs0, 1);
        rs0 += __shfl_xor_sync(FM, rs0, 2);
        rs1 += __shfl_xor_sync(FM, rs1, 1);
        rs1 += __shfl_xor_sync(FM, rs1, 2);
        PSM[ch * 128 + r0] = rs0;
        PSM[ch * 128 + r1] = rs1;

        // rescale O while waiting
#pragma unroll
        for (int nt = 0; nt < 8; nt++) {
            O[nt][0] *= fr0; O[nt][1] *= fr0;
            O[nt][2] *= fr1; O[nt][3] *= fr1;
        }
        // pending: {B(t)=V(t), A(t+1)} → wait(1) makes V(t) ready
        CP_WAIT(1);
        __syncthreads();   // sync3: P + psum + V(t) visible

        l0 = l0 * fr0 + PSM[r0] + PSM[128 + r0];
        l1 = l1 * fr1 + PSM[r1] + PSM[128 + r1];
        m0 = mn0; m1 = mn1;

        const uint32_t* Vb = (const uint32_t*)(smem_raw + OFF_V);

        // ---- gemm2: O[16 rows][64 cols of ch] += P V ----
#pragma unroll 1
        for (int ks = 0; ks < 8; ks++) {
            const int kr = ks * 8 + tig;
            uint32_t pa[4];
            pa[0] = Ps[r0 * PSTR + kr];
            pa[1] = Ps[r1 * PSTR + kr];
            pa[2] = Ps[r0 * PSTR + kr + 4];
            pa[3] = Ps[r1 * PSTR + kr + 4];
#pragma unroll
            for (int nt = 0; nt < 8; nt++) {
                const int col = ch * 64 + nt * 8 + g;
                uint32_t vb0 = Vb[kr * VSTR + col] + 0x1000u;
                uint32_t vb1 = Vb[(kr + 4) * VSTR + col] + 0x1000u;
                mma_tf32(O[nt], pa, vb0, vb1);
            }
        }

        __syncthreads();   // sync4: all warps done reading V(t)
        // ---- group B(t+1): prefetch V(t+1) into the (single) V buffer ----
        if (t + 1 < NITER) {
            const float* vt = vb + (size_t)(t + 1) * BK * DD;
#pragma unroll
            for (int i = 0; i < 4; i++) {
                int row = ldrow + i * 16;
                cp16(sbV + (uint32_t)(row * VSTR + ldc4) * 4u, vt + row * DD + ldc4);
            }
        }
        CP_COMMIT();
    }

    // ---- epilogue ----
    const float inv0 = 1.f / (l0 * 0.7f);
    const float inv1 = 1.f / (l1 * 0.7f);
    float* o0 = out + ((size_t)b * SS + gi0) * DD + ch * 64;
    float* o1 = out + ((size_t)b * SS + gi1) * DD + ch * 64;
#pragma unroll
    for (int nt = 0; nt < 8; nt++) {
        const int c = nt * 8 + 2 * tig;
        *(float2*)(o0 + c) = make_float2(O[nt][0] * inv0, O[nt][1] * inv0);
        *(float2*)(o1 + c) = make_float2(O[nt][2] * inv1, O[nt][3] * inv1);
    }
}

// ---------------------------------------------------------------------------
extern "C" void kernel_launch(void* const* d_in, const int* in_sizes, int n_in,
                              void* d_out, int out_size) {
    (void)in_sizes; (void)n_in; (void)out_size;
    const float* q = (const float*)d_in[0];
    const float* k = (const float*)d_in[1];
    const float* v = (const float*)d_in[2];
    const float* scale = (const float*)d_in[3];
    float* out = (float*)d_out;

    static const bool _init = []() {
        cudaFuncSetAttribute(attn_mma,
                             cudaFuncAttributeMaxDynamicSharedMemorySize,
                             SMEM_BYTES);
        return true;
    }();
    (void)_init;

    mask_kernel<<<(1 << 22) / MTH, MTH>>>();
    dim3 grid(SS / BQ, BB);
    attn_mma<<<grid, NTH, SMEM_BYTES>>>(q, k, v, scale, out);
}

// round 8
// speedup vs baseline: 1.1531x; 1.0001x over previous
#include <cuda_runtime.h>
#include <stdint.h>
#include <math.h>

#define BB 32
#define SS 2048
#define DD 128
#define BQ 128
#define BK 64
#define NITER (SS / BK)
#define NTH 512

// ===========================================================================
// threefry (partitionable, key (0,42)) — verified bit-exact in R2
// ===========================================================================
__device__ __forceinline__ uint32_t rotl32(uint32_t x, int r) {
    return __funnelshift_l(x, x, r);
}
#define TF_ROUND(r) do { x0 += x1; x1 = rotl32(x1, (r)); x1 ^= x0; } while (0)
__device__ __forceinline__ uint32_t threefry_fold_0_42(uint32_t c1) {
    const uint32_t ks1 = 42u, ks2 = 42u ^ 0x1BD11BDAu;
    uint32_t x0 = 0u, x1 = c1 + ks1;
    TF_ROUND(13); TF_ROUND(15); TF_ROUND(26); TF_ROUND(6);
    x0 += ks1; x1 += ks2 + 1u;
    TF_ROUND(17); TF_ROUND(29); TF_ROUND(16); TF_ROUND(24);
    x0 += ks2; x1 += 0u + 2u;
    TF_ROUND(13); TF_ROUND(15); TF_ROUND(26); TF_ROUND(6);
    x0 += 0u; x1 += ks1 + 3u;
    TF_ROUND(17); TF_ROUND(29); TF_ROUND(16); TF_ROUND(24);
    x0 += ks1; x1 += ks2 + 4u;
    TF_ROUND(13); TF_ROUND(15); TF_ROUND(26); TF_ROUND(6);
    x0 += ks2; x1 += 0u + 5u;
    return x0 ^ x1;
}
// 8 keep-bits at positions [sh, sh+8) for elements base..base+7
__device__ __forceinline__ uint32_t hash8_bits(uint32_t base, int sh) {
    const uint32_t TH = 3006477312u;    // 5872026 << 9
    uint32_t acc = 0u;
#pragma unroll
    for (int j = 0; j < 8; j++) {
        uint32_t bits = threefry_fold_0_42(base + (uint32_t)j);
        acc |= (bits < TH) ? (1u << (sh + j)) : 0u;
    }
    return acc;
}

// ===========================================================================
// mma.sync tf32 helpers
// ===========================================================================
__device__ __forceinline__ void mma_tf32(float* c, const uint32_t* a,
                                         uint32_t b0, uint32_t b1) {
    asm volatile(
        "mma.sync.aligned.m16n8k8.row.col.f32.tf32.tf32.f32 "
        "{%0,%1,%2,%3}, {%4,%5,%6,%7}, {%8,%9}, {%0,%1,%2,%3};"
        : "+f"(c[0]), "+f"(c[1]), "+f"(c[2]), "+f"(c[3])
        : "r"(a[0]), "r"(a[1]), "r"(a[2]), "r"(a[3]), "r"(b0), "r"(b1));
}
__device__ __forceinline__ uint32_t tf32_rna(float x) {
    uint32_t u;
    asm("cvt.rna.tf32.f32 %0, %1;" : "=r"(u) : "f"(x));
    return u;
}
__device__ __forceinline__ void split_tf32(float x, uint32_t& h, uint32_t& l) {
    uint32_t u = __float_as_uint(x);
    h = u & 0xffffe000u;
    float r = x - __uint_as_float(h);
    l = __float_as_uint(r) & 0xffffe000u;
}
__device__ __forceinline__ uint32_t smem_u32(const void* p) {
    uint32_t a;
    asm("{ .reg .u64 t; cvta.to.shared.u64 t, %1; cvt.u32.u64 %0, t; }"
        : "=r"(a) : "l"(p));
    return a;
}
__device__ __forceinline__ void cp16(uint32_t saddr, const void* g) {
    asm volatile("cp.async.cg.shared.global [%0], [%1], 16;"
                 :: "r"(saddr), "l"(g) : "memory");
}
#define CP_COMMIT() asm volatile("cp.async.commit_group;" ::: "memory")
#define CP_WAIT(n)  asm volatile("cp.async.wait_group %0;" :: "n"(n) : "memory")

// smem layout
#define QSTR 132
#define KSTR 132
#define VSTR 136
#define PSTR 68
#define OFF_Q 0
#define OFF_KA  (128 * QSTR * 4)          // 67584  raw K -> Khi in place
#define OFF_KLO (OFF_KA + 64 * KSTR * 4)  // 101376
#define OFF_V   (OFF_KLO + 64 * KSTR * 4) // 135168
#define OFF_P   (OFF_V + 64 * VSTR * 4)   // 169984
#define OFF_MX  (OFF_P + 128 * PSTR * 4)  // 204800  pmax [2][128]
#define OFF_SM  (OFF_MX + 1024)           // 205824  psum [2][128]
#define SMEM_BYTES (OFF_SM + 1024)        // 206848

__global__ void __launch_bounds__(NTH) attn_mma(
    const float* __restrict__ q, const float* __restrict__ k,
    const float* __restrict__ v, const float* __restrict__ scale,
    float* __restrict__ out) {
    extern __shared__ char smem_raw[];
    float* Qs = (float*)(smem_raw + OFF_Q);           // [128][132] scaled fp32
    float* KHI = (float*)(smem_raw + OFF_KA);         // [64][132]
    float* KLO = (float*)(smem_raw + OFF_KLO);        // [64][132]
    uint32_t* Ps = (uint32_t*)(smem_raw + OFF_P);     // [128][68] tf32 masked P
    float* PMX = (float*)(smem_raw + OFF_MX);         // [2][128]
    float* PSM = (float*)(smem_raw + OFF_SM);         // [2][128]
    const uint32_t sb = smem_u32(smem_raw);
    const uint32_t sbKA = sb + OFF_KA;
    const uint32_t sbV = sb + OFF_V;

    const int tid = threadIdx.x;
    const int lane = tid & 31;
    const int w = tid >> 5;           // 0..15
    const int rb = w >> 1;            // row block 0..7
    const int ch = w & 1;             // column half
    const int g = lane >> 2;
    const int tig = lane & 3;
    const int wrow = rb * 16;
    const int b = blockIdx.y;
    const int q0 = blockIdx.x * BQ;

    const float* kb = k + (size_t)b * SS * DD;
    const float* vb = v + (size_t)b * SS * DD;

    const int ldrow = tid >> 5;       // 0..15 ; 4 iters cover 64 rows
    const int ldc4 = (tid & 31) * 4;

    // ---- preload tile 0: group {K0}, group {V0} ----
#pragma unroll
    for (int i = 0; i < 4; i++) {
        int row = ldrow + i * 16;
        cp16(sbKA + (uint32_t)(row * KSTR + ldc4) * 4u, kb + row * DD + ldc4);
    }
    CP_COMMIT();
#pragma unroll
    for (int i = 0; i < 4; i++) {
        int row = ldrow + i * 16;
        cp16(sbV + (uint32_t)(row * VSTR + ldc4) * 4u, vb + row * DD + ldc4);
    }
    CP_COMMIT();

    // ---- load Q tile (scaled fp32) into smem (overlaps cp.async) ----
    {
        const float sc = scale[b];
        const float* qb = q + ((size_t)b * SS + q0) * DD;
#pragma unroll
        for (int i = 0; i < 8; i++) {
            int f = tid + i * NTH;          // 4096 float4
            int row = f >> 5, c4 = f & 31;
            float4 x = *(const float4*)(qb + row * DD + c4 * 4);
            float4 y = make_float4(x.x * sc, x.y * sc, x.z * sc, x.w * sc);
            *(float4*)(Qs + row * QSTR + c4 * 4) = y;
        }
    }

    const int r0 = wrow + g;
    const int r1 = wrow + g + 8;
    const int gi0 = q0 + r0;
    const int gi1 = q0 + r1;
    // element index bases for the dropout mask (32-elem word per row/half)
    const uint32_t ebase0 = (((uint32_t)b << 11) + (uint32_t)gi0) * 2048u
                            + (uint32_t)ch * 32u + (uint32_t)tig * 8u;
    const uint32_t ebase1 = (((uint32_t)b << 11) + (uint32_t)gi1) * 2048u
                            + (uint32_t)ch * 32u + (uint32_t)tig * 8u;
    const int tsh = tig * 8;
    const float L2E = 1.4426950408889634f;
    const uint32_t FM = 0xffffffffu;

    float m0 = -INFINITY, m1 = -INFINITY, l0 = 0.f, l1 = 0.f;
    float O[8][4];
#pragma unroll
    for (int nt = 0; nt < 8; nt++)
#pragma unroll
        for (int e = 0; e < 4; e++) O[nt][e] = 0.f;

    for (int t = 0; t < NITER; t++) {
        // pending: {K(t), V(t)} -> complete K(t)
        CP_WAIT(1);
        __syncthreads();   // sync0: raw K(t) visible; gemm2(t-1) done

        // ---- split phase: KA (raw) -> KHI (in place) + KLO ----
#pragma unroll
        for (int i = 0; i < 4; i++) {
            int f = tid + i * NTH;          // 2048 float4
            int row = f >> 5, c4 = (f & 31) * 4;
            int a = row * KSTR + c4;
            float4 x = *(const float4*)(KHI + a);
            uint32_t h0, lo0, h1, lo1, h2, lo2, h3, lo3;
            split_tf32(x.x, h0, lo0); split_tf32(x.y, h1, lo1);
            split_tf32(x.z, h2, lo2); split_tf32(x.w, h3, lo3);
            *(uint4*)(KHI + a) = make_uint4(h0, h1, h2, h3);
            *(uint4*)(KLO + a) = make_uint4(lo0, lo1, lo2, lo3);
        }
        __syncthreads();   // sync1: split done

        // ---- gemm1: S[16 rows][32 cols of ch] = Q K^T, 3-pass tf32 ----
        float S[4][4];
#pragma unroll
        for (int nt = 0; nt < 4; nt++)
#pragma unroll
            for (int e = 0; e < 4; e++) S[nt][e] = 0.f;

#pragma unroll 1
        for (int ks = 0; ks < 16; ks++) {
            const int kc = ks * 8 + tig;
            uint32_t ah[4], al[4];
            split_tf32(Qs[r0 * QSTR + kc], ah[0], al[0]);
            split_tf32(Qs[r1 * QSTR + kc], ah[1], al[1]);
            split_tf32(Qs[r0 * QSTR + kc + 4], ah[2], al[2]);
            split_tf32(Qs[r1 * QSTR + kc + 4], ah[3], al[3]);
#pragma unroll
            for (int nt = 0; nt < 4; nt++) {
                const int j = (ch * 32 + nt * 8 + g) * KSTR;
                uint32_t kh0 = ((const uint32_t*)KHI)[j + kc];
                uint32_t kh1 = ((const uint32_t*)KHI)[j + kc + 4];
                uint32_t kl0 = ((const uint32_t*)KLO)[j + kc];
                uint32_t kl1 = ((const uint32_t*)KLO)[j + kc + 4];
                mma_tf32(S[nt], ah, kh0, kh1);
                mma_tf32(S[nt], ah, kl0, kl1);
                mma_tf32(S[nt], al, kh0, kh1);
            }
        }

        // ---- softmax phase 1: partial row max ----
        float rmax0 = -INFINITY, rmax1 = -INFINITY;
#pragma unroll
        for (int nt = 0; nt < 4; nt++) {
            rmax0 = fmaxf(rmax0, fmaxf(S[nt][0], S[nt][1]));
            rmax1 = fmaxf(rmax1, fmaxf(S[nt][2], S[nt][3]));
        }
        rmax0 = fmaxf(rmax0, __shfl_xor_sync(FM, rmax0, 1));
        rmax0 = fmaxf(rmax0, __shfl_xor_sync(FM, rmax0, 2));
        rmax1 = fmaxf(rmax1, __shfl_xor_sync(FM, rmax1, 1));
        rmax1 = fmaxf(rmax1, __shfl_xor_sync(FM, rmax1, 2));
        PMX[ch * 128 + r0] = rmax0;
        PMX[ch * 128 + r1] = rmax1;
        __syncthreads();   // sync2: pmax visible; gemm1 done reading KA/KLO

        // ---- prefetch raw K(t+1) into KA ----
        if (t + 1 < NITER) {
            const float* kt = kb + (size_t)(t + 1) * BK * DD;
#pragma unroll
            for (int i = 0; i < 4; i++) {
                int row = ldrow + i * 16;
                cp16(sbKA + (uint32_t)(row * KSTR + ldc4) * 4u, kt + row * DD + ldc4);
            }
        }
        CP_COMMIT();       // pending: {V(t), K(t+1)}

        // ---- fused dropout mask: 16 threefry hashes, OR-combined over tig ----
        uint32_t mw0 = hash8_bits(ebase0 + (uint32_t)t * 64u, tsh);
        uint32_t mw1 = hash8_bits(ebase1 + (uint32_t)t * 64u, tsh);
        mw0 |= __shfl_xor_sync(FM, mw0, 1);
        mw0 |= __shfl_xor_sync(FM, mw0, 2);
        mw1 |= __shfl_xor_sync(FM, mw1, 1);
        mw1 |= __shfl_xor_sync(FM, mw1, 2);

        const float mn0 = fmaxf(m0, fmaxf(PMX[r0], PMX[128 + r0]));
        const float mn1 = fmaxf(m1, fmaxf(PMX[r1], PMX[128 + r1]));
        const float fr0 = exp2f((m0 - mn0) * L2E);
        const float fr1 = exp2f((m1 - mn1) * L2E);

        float rs0 = 0.f, rs1 = 0.f;
#pragma unroll
        for (int nt = 0; nt < 4; nt++) {
            const int c = nt * 8 + 2 * tig;     // local col in this 32-col half
            float e00 = exp2f((S[nt][0] - mn0) * L2E);
            float e01 = exp2f((S[nt][1] - mn0) * L2E);
            float e10 = exp2f((S[nt][2] - mn1) * L2E);
            float e11 = exp2f((S[nt][3] - mn1) * L2E);
            rs0 += e00 + e01;
            rs1 += e10 + e11;
            uint2 p0, p1;
            p0.x = ((mw0 >> c) & 1u) ? tf32_rna(e00) : 0u;
            p0.y = ((mw0 >> (c + 1)) & 1u) ? tf32_rna(e01) : 0u;
            p1.x = ((mw1 >> c) & 1u) ? tf32_rna(e10) : 0u;
            p1.y = ((mw1 >> (c + 1)) & 1u) ? tf32_rna(e11) : 0u;
            *(uint2*)(Ps + r0 * PSTR + ch * 32 + c) = p0;
            *(uint2*)(Ps + r1 * PSTR + ch * 32 + c) = p1;
        }
        rs0 += __shfl_xor_sync(FM, rs0, 1);
        rs0 += __shfl_xor_sync(FM, rs0, 2);
        rs1 += __shfl_xor_sync(FM, rs1, 1);
        rs1 += __shfl_xor_sync(FM, rs1, 2);
        PSM[ch * 128 + r0] = rs0;
        PSM[ch * 128 + r1] = rs1;

        // rescale O while waiting
#pragma unroll
        for (int nt = 0; nt < 8; nt++) {
            O[nt][0] *= fr0; O[nt][1] *= fr0;
            O[nt][2] *= fr1; O[nt][3] *= fr1;
        }
        // pending: {V(t), K(t+1)} -> complete V(t)
        CP_WAIT(1);
        __syncthreads();   // sync3: P + psum + V(t) visible

        l0 = l0 * fr0 + PSM[r0] + PSM[128 + r0];
        l1 = l1 * fr1 + PSM[r1] + PSM[128 + r1];
        m0 = mn0; m1 = mn1;

        const uint32_t* Vb = (const uint32_t*)(smem_raw + OFF_V);

        // ---- gemm2: O[16 rows][64 cols of ch] += P V ----
#pragma unroll 1
        for (int ks = 0; ks < 8; ks++) {
            const int kr = ks * 8 + tig;
            uint32_t pa[4];
            pa[0] = Ps[r0 * PSTR + kr];
            pa[1] = Ps[r1 * PSTR + kr];
            pa[2] = Ps[r0 * PSTR + kr + 4];
            pa[3] = Ps[r1 * PSTR + kr + 4];
#pragma unroll
            for (int nt = 0; nt < 8; nt++) {
                const int col = ch * 64 + nt * 8 + g;
                uint32_t vb0 = Vb[kr * VSTR + col] + 0x1000u;
                uint32_t vb1 = Vb[(kr + 4) * VSTR + col] + 0x1000u;
                mma_tf32(O[nt], pa, vb0, vb1);
            }
        }

        __syncthreads();   // sync4: all warps done reading V(t)
        // ---- prefetch V(t+1) into the (single) V buffer ----
        if (t + 1 < NITER) {
            const float* vt = vb + (size_t)(t + 1) * BK * DD;
#pragma unroll
            for (int i = 0; i < 4; i++) {
                int row = ldrow + i * 16;
                cp16(sbV + (uint32_t)(row * VSTR + ldc4) * 4u, vt + row * DD + ldc4);
            }
        }
        CP_COMMIT();       // pending: {K(t+1), V(t+1)}
    }

    // ---- epilogue ----
    const float inv0 = 1.f / (l0 * 0.7f);
    const float inv1 = 1.f / (l1 * 0.7f);
    float* o0 = out + ((size_t)b * SS + gi0) * DD + ch * 64;
    float* o1 = out + ((size_t)b * SS + gi1) * DD + ch * 64;
#pragma unroll
    for (int nt = 0; nt < 8; nt++) {
        const int c = nt * 8 + 2 * tig;
        *(float2*)(o0 + c) = make_float2(O[nt][0] * inv0, O[nt][1] * inv0);
        *(float2*)(o1 + c) = make_float2(O[nt][2] * inv1, O[nt][3] * inv1);
    }
}

// ---------------------------------------------------------------------------
extern "C" void kernel_launch(void* const* d_in, const int* in_sizes, int n_in,
                              void* d_out, int out_size) {
    (void)in_sizes; (void)n_in; (void)out_size;
    const float* q = (const float*)d_in[0];
    const float* k = (const float*)d_in[1];
    const float* v = (const float*)d_in[2];
    const float* scale = (const float*)d_in[3];
    float* out = (float*)d_out;

    static const bool _init = []() {
        cudaFuncSetAttribute(attn_mma,
                             cudaFuncAttributeMaxDynamicSharedMemorySize,
                             SMEM_BYTES);
        return true;
    }();
    (void)_init;

    dim3 grid(SS / BQ, BB);
    attn_mma<<<grid, NTH, SMEM_BYTES>>>(q, k, v, scale, out);
}

// round 9
// speedup vs baseline: 1.5270x; 1.3243x over previous
#include <cuda_runtime.h>
#include <cuda_fp16.h>
#include <stdint.h>
#include <math.h>

#define BB 32
#define SS 2048
#define DD 128
#define BQ 128
#define BK 64
#define NITER (SS / BK)
#define NTH 512

// ===========================================================================
// threefry (partitionable, key (0,42)) — verified bit-exact in R2/R8
// ===========================================================================
__device__ __forceinline__ uint32_t rotl32(uint32_t x, int r) {
    return __funnelshift_l(x, x, r);
}
#define TF_ROUND(r) do { x0 += x1; x1 = rotl32(x1, (r)); x1 ^= x0; } while (0)
__device__ __forceinline__ uint32_t threefry_fold_0_42(uint32_t c1) {
    const uint32_t ks1 = 42u, ks2 = 42u ^ 0x1BD11BDAu;
    uint32_t x0 = 0u, x1 = c1 + ks1;
    TF_ROUND(13); TF_ROUND(15); TF_ROUND(26); TF_ROUND(6);
    x0 += ks1; x1 += ks2 + 1u;
    TF_ROUND(17); TF_ROUND(29); TF_ROUND(16); TF_ROUND(24);
    x0 += ks2; x1 += 0u + 2u;
    TF_ROUND(13); TF_ROUND(15); TF_ROUND(26); TF_ROUND(6);
    x0 += 0u; x1 += ks1 + 3u;
    TF_ROUND(17); TF_ROUND(29); TF_ROUND(16); TF_ROUND(24);
    x0 += ks1; x1 += ks2 + 4u;
    TF_ROUND(13); TF_ROUND(15); TF_ROUND(26); TF_ROUND(6);
    x0 += ks2; x1 += 0u + 5u;
    return x0 ^ x1;
}
__device__ __forceinline__ uint32_t hash8_bits(uint32_t base, int sh) {
    const uint32_t TH = 3006477312u;    // 5872026 << 9
    uint32_t acc = 0u;
#pragma unroll
    for (int j = 0; j < 8; j++) {
        uint32_t bits = threefry_fold_0_42(base + (uint32_t)j);
        acc |= (bits < TH) ? (1u << (sh + j)) : 0u;
    }
    return acc;
}

// ===========================================================================
// fp16 mma + pack helpers
// ===========================================================================
__device__ __forceinline__ void mma_f16(float* c, const uint32_t* a,
                                        uint32_t b0, uint32_t b1) {
    asm volatile(
        "mma.sync.aligned.m16n8k16.row.col.f32.f16.f16.f32 "
        "{%0,%1,%2,%3}, {%4,%5,%6,%7}, {%8,%9}, {%0,%1,%2,%3};"
        : "+f"(c[0]), "+f"(c[1]), "+f"(c[2]), "+f"(c[3])
        : "r"(a[0]), "r"(a[1]), "r"(a[2]), "r"(a[3]), "r"(b0), "r"(b1));
}
// pack {low half <- lo, high half <- hi}
__device__ __forceinline__ uint32_t packh2(float lo, float hi) {
    uint32_t d;
    asm("cvt.rn.f16x2.f32 %0, %1, %2;" : "=r"(d) : "f"(hi), "f"(lo));
    return d;
}
__device__ __forceinline__ float2 h2f2(uint32_t h) {
    __half2 v = *reinterpret_cast<__half2*>(&h);
    return __half22float2(v);
}
// split two fp32 into packed hi (rn) and packed lo (residual)
__device__ __forceinline__ void split2(float x, float y, uint32_t& hw, uint32_t& lw) {
    hw = packh2(x, y);
    float2 f = h2f2(hw);
    lw = packh2(x - f.x, y - f.y);
}
__device__ __forceinline__ uint32_t smem_u32(const void* p) {
    uint32_t a;
    asm("{ .reg .u64 t; cvta.to.shared.u64 t, %1; cvt.u32.u64 %0, t; }"
        : "=r"(a) : "l"(p));
    return a;
}
__device__ __forceinline__ void cp16(uint32_t saddr, const void* g) {
    asm volatile("cp.async.cg.shared.global [%0], [%1], 16;"
                 :: "r"(saddr), "l"(g) : "memory");
}
#define CP_COMMIT() asm volatile("cp.async.commit_group;" ::: "memory")
#define CP_WAIT(n)  asm volatile("cp.async.wait_group %0;" :: "n"(n) : "memory")

// ---- smem layout (word strides) ----
#define QPSTR 68      // packed Q rows (words)
#define KPSTR 68      // packed K rows (words)
#define KRSTR 132     // raw K rows (fp32 words)
#define VRSTR 132     // raw V rows
#define VPSTR 136     // packed V keypair rows (words over d)
#define PPSTR 36      // packed P rows (words)

#define OFF_QH 0
#define OFF_QL (OFF_QH + 128 * QPSTR * 4)    // 34816
#define OFF_KRAW (OFF_QL + 128 * QPSTR * 4)  // 69632
#define OFF_KH (OFF_KRAW + 64 * KRSTR * 4)   // 103424
#define OFF_KL (OFF_KH + 64 * KPSTR * 4)     // 120832
#define OFF_VRAW (OFF_KL + 64 * KPSTR * 4)   // 138240
#define OFF_VP (OFF_VRAW + 64 * VRSTR * 4)   // 172032
#define OFF_P (OFF_VP + 32 * VPSTR * 4)      // 189440
#define OFF_MX (OFF_P + 128 * PPSTR * 4)     // 207872
#define OFF_SM (OFF_MX + 1024)               // 208896
#define SMEM_BYTES (OFF_SM + 1024)           // 209920

__global__ void __launch_bounds__(NTH) attn_mma(
    const float* __restrict__ q, const float* __restrict__ k,
    const float* __restrict__ v, const float* __restrict__ scale,
    float* __restrict__ out) {
    extern __shared__ char smem_raw[];
    uint32_t* QH = (uint32_t*)(smem_raw + OFF_QH);
    uint32_t* QL = (uint32_t*)(smem_raw + OFF_QL);
    float* KRAW = (float*)(smem_raw + OFF_KRAW);
    uint32_t* KH = (uint32_t*)(smem_raw + OFF_KH);
    uint32_t* KL = (uint32_t*)(smem_raw + OFF_KL);
    float* VRAW = (float*)(smem_raw + OFF_VRAW);
    uint32_t* VP = (uint32_t*)(smem_raw + OFF_VP);
    uint32_t* PP = (uint32_t*)(smem_raw + OFF_P);
    float* PMX = (float*)(smem_raw + OFF_MX);
    float* PSM = (float*)(smem_raw + OFF_SM);
    const uint32_t sb = smem_u32(smem_raw);
    const uint32_t sbKR = sb + OFF_KRAW;
    const uint32_t sbVR = sb + OFF_VRAW;

    const int tid = threadIdx.x;
    const int lane = tid & 31;
    const int w = tid >> 5;
    const int rb = w >> 1;
    const int ch = w & 1;
    const int g = lane >> 2;
    const int tig = lane & 3;
    const int wrow = rb * 16;
    const int b = blockIdx.y;
    const int q0 = blockIdx.x * BQ;

    const float* kb = k + (size_t)b * SS * DD;
    const float* vb = v + (size_t)b * SS * DD;

    const int ldrow = tid >> 5;
    const int ldc4 = (tid & 31) * 4;

    // ---- preload tile 0: {K0}, {V0} ----
#pragma unroll
    for (int i = 0; i < 4; i++) {
        int row = ldrow + i * 16;
        cp16(sbKR + (uint32_t)(row * KRSTR + ldc4) * 4u, kb + row * DD + ldc4);
    }
    CP_COMMIT();
#pragma unroll
    for (int i = 0; i < 4; i++) {
        int row = ldrow + i * 16;
        cp16(sbVR + (uint32_t)(row * VRSTR + ldc4) * 4u, vb + row * DD + ldc4);
    }
    CP_COMMIT();

    // ---- prologue: load Q, scale, split to packed fp16 hi/lo ----
    {
        const float sc = scale[b];
        const float* qb = q + ((size_t)b * SS + q0) * DD;
#pragma unroll
        for (int i = 0; i < 8; i++) {
            int f = tid + i * NTH;          // 4096 float4
            int row = f >> 5, cq = f & 31;
            float4 x = *(const float4*)(qb + row * DD + cq * 4);
            uint32_t h0, l0w, h1, l1w;
            split2(x.x * sc, x.y * sc, h0, l0w);
            split2(x.z * sc, x.w * sc, h1, l1w);
            *(uint2*)(QH + row * QPSTR + cq * 2) = make_uint2(h0, h1);
            *(uint2*)(QL + row * QPSTR + cq * 2) = make_uint2(l0w, l1w);
        }
    }

    const int r0 = wrow + g;
    const int r1 = wrow + g + 8;
    const int gi0 = q0 + r0;
    const int gi1 = q0 + r1;
    const uint32_t ebase0 = (((uint32_t)b << 11) + (uint32_t)gi0) * 2048u
                            + (uint32_t)ch * 32u + (uint32_t)tig * 8u;
    const uint32_t ebase1 = (((uint32_t)b << 11) + (uint32_t)gi1) * 2048u
                            + (uint32_t)ch * 32u + (uint32_t)tig * 8u;
    const int tsh = tig * 8;
    const float L2E = 1.4426950408889634f;
    const uint32_t FM = 0xffffffffu;

    float m0 = -INFINITY, m1 = -INFINITY, l0 = 0.f, l1 = 0.f;
    float O[8][4];
#pragma unroll
    for (int nt = 0; nt < 8; nt++)
#pragma unroll
        for (int e = 0; e < 4; e++) O[nt][e] = 0.f;

    for (int t = 0; t < NITER; t++) {
        // pending {K(t), V(t)} -> complete K(t)
        CP_WAIT(1);
        __syncthreads();   // A: raw K(t) visible; gemm2(t-1) done (VP/PP free)

        // ---- split K raw -> packed KH/KL ----
#pragma unroll
        for (int i = 0; i < 4; i++) {
            int f = tid + i * NTH;          // 2048 float4
            int row = f >> 5, cq = f & 31;
            float4 x = *(const float4*)(KRAW + row * KRSTR + cq * 4);
            uint32_t h0, l0w, h1, l1w;
            split2(x.x, x.y, h0, l0w);
            split2(x.z, x.w, h1, l1w);
            *(uint2*)(KH + row * KPSTR + cq * 2) = make_uint2(h0, h1);
            *(uint2*)(KL + row * KPSTR + cq * 2) = make_uint2(l0w, l1w);
        }
        __syncthreads();   // B: KH/KL visible; KRAW free

        // ---- prefetch raw K(t+1) ----
        if (t + 1 < NITER) {
            const float* kt = kb + (size_t)(t + 1) * BK * DD;
#pragma unroll
            for (int i = 0; i < 4; i++) {
                int row = ldrow + i * 16;
                cp16(sbKR + (uint32_t)(row * KRSTR + ldc4) * 4u, kt + row * DD + ldc4);
            }
        }
        CP_COMMIT();       // pending {V(t), K(t+1)}

        // ---- gemm1: S[16r][32c of ch] = Q K^T, 3-pass split-fp16 k16 ----
        float S[4][4];
#pragma unroll
        for (int nt = 0; nt < 4; nt++)
#pragma unroll
            for (int e = 0; e < 4; e++) S[nt][e] = 0.f;

#pragma unroll 1
        for (int ks = 0; ks < 8; ks++) {
            const int wq = ks * 8 + tig;
            uint32_t ah[4], al[4];
            ah[0] = QH[r0 * QPSTR + wq];     al[0] = QL[r0 * QPSTR + wq];
            ah[1] = QH[r1 * QPSTR + wq];     al[1] = QL[r1 * QPSTR + wq];
            ah[2] = QH[r0 * QPSTR + wq + 4]; al[2] = QL[r0 * QPSTR + wq + 4];
            ah[3] = QH[r1 * QPSTR + wq + 4]; al[3] = QL[r1 * QPSTR + wq + 4];
#pragma unroll
            for (int nt = 0; nt < 4; nt++) {
                const int j = (ch * 32 + nt * 8 + g) * KPSTR;
                uint32_t bh0 = KH[j + wq], bh1 = KH[j + wq + 4];
                uint32_t bl0 = KL[j + wq], bl1 = KL[j + wq + 4];
                mma_f16(S[nt], ah, bh0, bh1);
                mma_f16(S[nt], ah, bl0, bl1);
                mma_f16(S[nt], al, bh0, bh1);
            }
        }

        // ---- partial row max ----
        float rmax0 = -INFINITY, rmax1 = -INFINITY;
#pragma unroll
        for (int nt = 0; nt < 4; nt++) {
            rmax0 = fmaxf(rmax0, fmaxf(S[nt][0], S[nt][1]));
            rmax1 = fmaxf(rmax1, fmaxf(S[nt][2], S[nt][3]));
        }
        rmax0 = fmaxf(rmax0, __shfl_xor_sync(FM, rmax0, 1));
        rmax0 = fmaxf(rmax0, __shfl_xor_sync(FM, rmax0, 2));
        rmax1 = fmaxf(rmax1, __shfl_xor_sync(FM, rmax1, 1));
        rmax1 = fmaxf(rmax1, __shfl_xor_sync(FM, rmax1, 2));
        PMX[ch * 128 + r0] = rmax0;
        PMX[ch * 128 + r1] = rmax1;
        __syncthreads();   // C: pmax visible

        // ---- fused dropout mask ----
        uint32_t mw0 = hash8_bits(ebase0 + (uint32_t)t * 64u, tsh);
        uint32_t mw1 = hash8_bits(ebase1 + (uint32_t)t * 64u, tsh);
        mw0 |= __shfl_xor_sync(FM, mw0, 1);
        mw0 |= __shfl_xor_sync(FM, mw0, 2);
        mw1 |= __shfl_xor_sync(FM, mw1, 1);
        mw1 |= __shfl_xor_sync(FM, mw1, 2);

        const float mn0 = fmaxf(m0, fmaxf(PMX[r0], PMX[128 + r0]));
        const float mn1 = fmaxf(m1, fmaxf(PMX[r1], PMX[128 + r1]));
        const float fr0 = exp2f((m0 - mn0) * L2E);
        const float fr1 = exp2f((m1 - mn1) * L2E);

        float rs0 = 0.f, rs1 = 0.f;
#pragma unroll
        for (int nt = 0; nt < 4; nt++) {
            const int c = nt * 8 + 2 * tig;
            float e00 = exp2f((S[nt][0] - mn0) * L2E);
            float e01 = exp2f((S[nt][1] - mn0) * L2E);
            float e10 = exp2f((S[nt][2] - mn1) * L2E);
            float e11 = exp2f((S[nt][3] - mn1) * L2E);
            rs0 += e00 + e01;
            rs1 += e10 + e11;
            float d00 = ((mw0 >> c) & 1u) ? e00 : 0.f;
            float d01 = ((mw0 >> (c + 1)) & 1u) ? e01 : 0.f;
            float d10 = ((mw1 >> c) & 1u) ? e10 : 0.f;
            float d11 = ((mw1 >> (c + 1)) & 1u) ? e11 : 0.f;
            const int pw = ch * 16 + nt * 4 + tig;   // packed word index
            PP[r0 * PPSTR + pw] = packh2(d00, d01);
            PP[r1 * PPSTR + pw] = packh2(d10, d11);
        }
        rs0 += __shfl_xor_sync(FM, rs0, 1);
        rs0 += __shfl_xor_sync(FM, rs0, 2);
        rs1 += __shfl_xor_sync(FM, rs1, 1);
        rs1 += __shfl_xor_sync(FM, rs1, 2);
        PSM[ch * 128 + r0] = rs0;
        PSM[ch * 128 + r1] = rs1;

        // pending {V(t), K(t+1)} -> complete V(t)
        CP_WAIT(1);
        __syncthreads();   // D: PP + PSM + raw V(t) visible

        l0 = l0 * fr0 + PSM[r0] + PSM[128 + r0];
        l1 = l1 * fr1 + PSM[r1] + PSM[128 + r1];
        m0 = mn0; m1 = mn1;

        // ---- pack V raw -> VP[keypair][d] fp16x2 over key pairs ----
        {
            const int kp = tid >> 4;            // 0..31
            const int d0 = (tid & 15) * 8;      // 8 d-columns
#pragma unroll
            for (int h = 0; h < 2; h++) {
                const int dd = d0 + h * 4;
                float4 a = *(const float4*)(VRAW + (2 * kp) * VRSTR + dd);
                float4 c2 = *(const float4*)(VRAW + (2 * kp + 1) * VRSTR + dd);
                uint4 o;
                o.x = packh2(a.x, c2.x);
                o.y = packh2(a.y, c2.y);
                o.z = packh2(a.z, c2.z);
                o.w = packh2(a.w, c2.w);
                *(uint4*)(VP + kp * VPSTR + dd) = o;
            }
        }
        // rescale O while pack settles
#pragma unroll
        for (int nt = 0; nt < 8; nt++) {
            O[nt][0] *= fr0; O[nt][1] *= fr0;
            O[nt][2] *= fr1; O[nt][3] *= fr1;
        }
        __syncthreads();   // E: VP visible; VRAW free

        // ---- prefetch raw V(t+1) ----
        if (t + 1 < NITER) {
            const float* vt = vb + (size_t)(t + 1) * BK * DD;
#pragma unroll
            for (int i = 0; i < 4; i++) {
                int row = ldrow + i * 16;
                cp16(sbVR + (uint32_t)(row * VRSTR + ldc4) * 4u, vt + row * DD + ldc4);
            }
        }
        CP_COMMIT();       // pending {K(t+1), V(t+1)}

        // ---- gemm2: O[16r][64c of ch] += P V, fp16 k16 ----
#pragma unroll 1
        for (int ks = 0; ks < 4; ks++) {
            const int wp = ks * 8 + tig;
            uint32_t pa[4];
            pa[0] = PP[r0 * PPSTR + wp];
            pa[1] = PP[r1 * PPSTR + wp];
            pa[2] = PP[r0 * PPSTR + wp + 4];
            pa[3] = PP[r1 * PPSTR + wp + 4];
#pragma unroll
            for (int nt = 0; nt < 8; nt++) {
                const int col = ch * 64 + nt * 8 + g;
                uint32_t vb0 = VP[wp * VPSTR + col];
                uint32_t vb1 = VP[(wp + 4) * VPSTR + col];
                mma_f16(O[nt], pa, vb0, vb1);
            }
        }
    }

    // ---- epilogue ----
    const float inv0 = 1.f / (l0 * 0.7f);
    const float inv1 = 1.f / (l1 * 0.7f);
    float* o0 = out + ((size_t)b * SS + gi0) * DD + ch * 64;
    float* o1 = out + ((size_t)b * SS + gi1) * DD + ch * 64;
#pragma unroll
    for (int nt = 0; nt < 8; nt++) {
        const int c = nt * 8 + 2 * tig;
        *(float2*)(o0 + c) = make_float2(O[nt][0] * inv0, O[nt][1] * inv0);
        *(float2*)(o1 + c) = make_float2(O[nt][2] * inv1, O[nt][3] * inv1);
    }
}

// ---------------------------------------------------------------------------
extern "C" void kernel_launch(void* const* d_in, const int* in_sizes, int n_in,
                              void* d_out, int out_size) {
    (void)in_sizes; (void)n_in; (void)out_size;
    const float* q = (const float*)d_in[0];
    const float* k = (const float*)d_in[1];
    const float* v = (const float*)d_in[2];
    const float* scale = (const float*)d_in[3];
    float* out = (float*)d_out;

    static const bool _init = []() {
        cudaFuncSetAttribute(attn_mma,
                             cudaFuncAttributeMaxDynamicSharedMemorySize,
                             SMEM_BYTES);
        return true;
    }();
    (void)_init;

    dim3 grid(SS / BQ, BB);
    attn_mma<<<grid, NTH, SMEM_BYTES>>>(q, k, v, scale, out);
}

// round 10
// speedup vs baseline: 1.9452x; 1.2738x over previous
#include <cuda_runtime.h>
#include <cuda_fp16.h>
#include <stdint.h>
#include <math.h>

#define BB 32
#define SS 2048
#define DD 128
#define BQ 128
#define BK 64
#define NITER (SS / BK)
#define NTH 512

// ===========================================================================
// threefry (partitionable, key (0,42)) — verified bit-exact in R2/R8/R9
// ===========================================================================
__device__ __forceinline__ uint32_t rotl32(uint32_t x, int r) {
    return __funnelshift_l(x, x, r);
}
#define TF_ROUND(r) do { x0 += x1; x1 = rotl32(x1, (r)); x1 ^= x0; } while (0)
__device__ __forceinline__ uint32_t threefry_fold_0_42(uint32_t c1) {
    const uint32_t ks1 = 42u, ks2 = 42u ^ 0x1BD11BDAu;
    uint32_t x0 = 0u, x1 = c1 + ks1;
    TF_ROUND(13); TF_ROUND(15); TF_ROUND(26); TF_ROUND(6);
    x0 += ks1; x1 += ks2 + 1u;
    TF_ROUND(17); TF_ROUND(29); TF_ROUND(16); TF_ROUND(24);
    x0 += ks2; x1 += 0u + 2u;
    TF_ROUND(13); TF_ROUND(15); TF_ROUND(26); TF_ROUND(6);
    x0 += 0u; x1 += ks1 + 3u;
    TF_ROUND(17); TF_ROUND(29); TF_ROUND(16); TF_ROUND(24);
    x0 += ks1; x1 += ks2 + 4u;
    TF_ROUND(13); TF_ROUND(15); TF_ROUND(26); TF_ROUND(6);
    x0 += ks2; x1 += 0u + 5u;
    return x0 ^ x1;
}
// 8 keep-bits for this lane's own columns: (nt,e) -> bit nt*2+e,
// element counter = cb + nt*8 + e
__device__ __forceinline__ uint32_t hash8_scatter(uint32_t cb) {
    const uint32_t TH = 3006477312u;    // 5872026 << 9
    uint32_t acc = 0u;
#pragma unroll
    for (int nt = 0; nt < 4; nt++) {
#pragma unroll
        for (int e = 0; e < 2; e++) {
            uint32_t bits = threefry_fold_0_42(cb + (uint32_t)(nt * 8 + e));
            acc |= (bits < TH) ? (1u << (nt * 2 + e)) : 0u;
        }
    }
    return acc;
}

// ===========================================================================
// fp16 mma + pack helpers
// ===========================================================================
__device__ __forceinline__ void mma_f16(float* c, const uint32_t* a,
                                        uint32_t b0, uint32_t b1) {
    asm volatile(
        "mma.sync.aligned.m16n8k16.row.col.f32.f16.f16.f32 "
        "{%0,%1,%2,%3}, {%4,%5,%6,%7}, {%8,%9}, {%0,%1,%2,%3};"
        : "+f"(c[0]), "+f"(c[1]), "+f"(c[2]), "+f"(c[3])
        : "r"(a[0]), "r"(a[1]), "r"(a[2]), "r"(a[3]), "r"(b0), "r"(b1));
}
__device__ __forceinline__ uint32_t packh2(float lo, float hi) {
    uint32_t d;
    asm("cvt.rn.f16x2.f32 %0, %1, %2;" : "=r"(d) : "f"(hi), "f"(lo));
    return d;
}
__device__ __forceinline__ float2 h2f2(uint32_t h) {
    __half2 v = *reinterpret_cast<__half2*>(&h);
    return __half22float2(v);
}
__device__ __forceinline__ void split2(float x, float y, uint32_t& hw, uint32_t& lw) {
    hw = packh2(x, y);
    float2 f = h2f2(hw);
    lw = packh2(x - f.x, y - f.y);
}
__device__ __forceinline__ uint32_t smem_u32(const void* p) {
    uint32_t a;
    asm("{ .reg .u64 t; cvta.to.shared.u64 t, %1; cvt.u32.u64 %0, t; }"
        : "=r"(a) : "l"(p));
    return a;
}
__device__ __forceinline__ void cp16(uint32_t saddr, const void* g) {
    asm volatile("cp.async.cg.shared.global [%0], [%1], 16;"
                 :: "r"(saddr), "l"(g) : "memory");
}
#define CP_COMMIT() asm volatile("cp.async.commit_group;" ::: "memory")
#define CP_WAIT(n)  asm volatile("cp.async.wait_group %0;" :: "n"(n) : "memory")

// ---- smem layout (word strides) ----
#define QPSTR 68
#define KPSTR 68
#define KRSTR 132
#define VRSTR 132
#define VPSTR 136
#define PPSTR 36

#define OFF_QH 0
#define OFF_QL (OFF_QH + 128 * QPSTR * 4)    // 34816
#define OFF_KRAW (OFF_QL + 128 * QPSTR * 4)  // 69632
#define OFF_KH (OFF_KRAW + 64 * KRSTR * 4)   // 103424
#define OFF_KL (OFF_KH + 64 * KPSTR * 4)     // 120832
#define OFF_VRAW (OFF_KL + 64 * KPSTR * 4)   // 138240
#define OFF_VP (OFF_VRAW + 64 * VRSTR * 4)   // 172032
#define OFF_P (OFF_VP + 32 * VPSTR * 4)      // 189440
#define OFF_MX (OFF_P + 128 * PPSTR * 4)     // 207872
#define OFF_SM (OFF_MX + 1024)               // 208896
#define SMEM_BYTES (OFF_SM + 1024)           // 209920

__global__ void __launch_bounds__(NTH) attn_mma(
    const float* __restrict__ q, const float* __restrict__ k,
    const float* __restrict__ v, const float* __restrict__ scale,
    float* __restrict__ out) {
    extern __shared__ char smem_raw[];
    uint32_t* QH = (uint32_t*)(smem_raw + OFF_QH);
    uint32_t* QL = (uint32_t*)(smem_raw + OFF_QL);
    float* KRAW = (float*)(smem_raw + OFF_KRAW);
    uint32_t* KH = (uint32_t*)(smem_raw + OFF_KH);
    uint32_t* KL = (uint32_t*)(smem_raw + OFF_KL);
    float* VRAW = (float*)(smem_raw + OFF_VRAW);
    uint32_t* VP = (uint32_t*)(smem_raw + OFF_VP);
    uint32_t* PP = (uint32_t*)(smem_raw + OFF_P);
    float* PMX = (float*)(smem_raw + OFF_MX);
    float* PSM = (float*)(smem_raw + OFF_SM);
    const uint32_t sb = smem_u32(smem_raw);
    const uint32_t sbKR = sb + OFF_KRAW;
    const uint32_t sbVR = sb + OFF_VRAW;

    const int tid = threadIdx.x;
    const int lane = tid & 31;
    const int w = tid >> 5;
    const int rb = w >> 1;
    const int ch = w & 1;
    const int g = lane >> 2;
    const int tig = lane & 3;
    const int wrow = rb * 16;
    const int b = blockIdx.y;
    const int q0 = blockIdx.x * BQ;

    const float* kb = k + (size_t)b * SS * DD;
    const float* vb = v + (size_t)b * SS * DD;

    const int ldrow = tid >> 5;
    const int ldc4 = (tid & 31) * 4;

    // ---- preload tile 0: {K0}, {V0} ----
#pragma unroll
    for (int i = 0; i < 4; i++) {
        int row = ldrow + i * 16;
        cp16(sbKR + (uint32_t)(row * KRSTR + ldc4) * 4u, kb + row * DD + ldc4);
    }
    CP_COMMIT();
#pragma unroll
    for (int i = 0; i < 4; i++) {
        int row = ldrow + i * 16;
        cp16(sbVR + (uint32_t)(row * VRSTR + ldc4) * 4u, vb + row * DD + ldc4);
    }
    CP_COMMIT();

    // ---- prologue: load Q, scale, split to packed fp16 hi/lo ----
    {
        const float sc = scale[b];
        const float* qb = q + ((size_t)b * SS + q0) * DD;
#pragma unroll
        for (int i = 0; i < 8; i++) {
            int f = tid + i * NTH;
            int row = f >> 5, cq = f & 31;
            float4 x = *(const float4*)(qb + row * DD + cq * 4);
            uint32_t h0, l0w, h1, l1w;
            split2(x.x * sc, x.y * sc, h0, l0w);
            split2(x.z * sc, x.w * sc, h1, l1w);
            *(uint2*)(QH + row * QPSTR + cq * 2) = make_uint2(h0, h1);
            *(uint2*)(QL + row * QPSTR + cq * 2) = make_uint2(l0w, l1w);
        }
    }

    const int r0 = wrow + g;
    const int r1 = wrow + g + 8;
    const int gi0 = q0 + r0;
    const int gi1 = q0 + r1;
    // counter base for this lane's own mask bits
    const uint32_t cbase0 = (((uint32_t)b << 11) + (uint32_t)gi0) * 2048u
                            + (uint32_t)ch * 32u + (uint32_t)tig * 2u;
    const uint32_t cbase1 = (((uint32_t)b << 11) + (uint32_t)gi1) * 2048u
                            + (uint32_t)ch * 32u + (uint32_t)tig * 2u;
    const float L2E = 1.4426950408889634f;
    const float DEAD = -17.3286795139986f;   // -25*ln2: below this, fp16(e)==0
    const uint32_t FM = 0xffffffffu;

    float m0 = -INFINITY, m1 = -INFINITY, l0 = 0.f, l1 = 0.f;
    float O[8][4];
#pragma unroll
    for (int nt = 0; nt < 8; nt++)
#pragma unroll
        for (int e = 0; e < 4; e++) O[nt][e] = 0.f;

    for (int t = 0; t < NITER; t++) {
        CP_WAIT(1);
        __syncthreads();   // A: raw K(t) visible; gemm2(t-1) done

        // ---- split K raw -> packed KH/KL ----
#pragma unroll
        for (int i = 0; i < 4; i++) {
            int f = tid + i * NTH;
            int row = f >> 5, cq = f & 31;
            float4 x = *(const float4*)(KRAW + row * KRSTR + cq * 4);
            uint32_t h0, l0w, h1, l1w;
            split2(x.x, x.y, h0, l0w);
            split2(x.z, x.w, h1, l1w);
            *(uint2*)(KH + row * KPSTR + cq * 2) = make_uint2(h0, h1);
            *(uint2*)(KL + row * KPSTR + cq * 2) = make_uint2(l0w, l1w);
        }
        __syncthreads();   // B: KH/KL visible; KRAW free

        if (t + 1 < NITER) {
            const float* kt = kb + (size_t)(t + 1) * BK * DD;
#pragma unroll
            for (int i = 0; i < 4; i++) {
                int row = ldrow + i * 16;
                cp16(sbKR + (uint32_t)(row * KRSTR + ldc4) * 4u, kt + row * DD + ldc4);
            }
        }
        CP_COMMIT();       // pending {V(t), K(t+1)}

        // ---- gemm1: 3-pass split-fp16 k16 ----
        float S[4][4];
#pragma unroll
        for (int nt = 0; nt < 4; nt++)
#pragma unroll
            for (int e = 0; e < 4; e++) S[nt][e] = 0.f;

#pragma unroll 1
        for (int ks = 0; ks < 8; ks++) {
            const int wq = ks * 8 + tig;
            uint32_t ah[4], al[4];
            ah[0] = QH[r0 * QPSTR + wq];     al[0] = QL[r0 * QPSTR + wq];
            ah[1] = QH[r1 * QPSTR + wq];     al[1] = QL[r1 * QPSTR + wq];
            ah[2] = QH[r0 * QPSTR + wq + 4]; al[2] = QL[r0 * QPSTR + wq + 4];
            ah[3] = QH[r1 * QPSTR + wq + 4]; al[3] = QL[r1 * QPSTR + wq + 4];
#pragma unroll
            for (int nt = 0; nt < 4; nt++) {
                const int j = (ch * 32 + nt * 8 + g) * KPSTR;
                uint32_t bh0 = KH[j + wq], bh1 = KH[j + wq + 4];
                uint32_t bl0 = KL[j + wq], bl1 = KL[j + wq + 4];
                mma_f16(S[nt], ah, bh0, bh1);
                mma_f16(S[nt], ah, bl0, bl1);
                mma_f16(S[nt], al, bh0, bh1);
            }
        }

        // ---- partial row max ----
        float rmax0 = -INFINITY, rmax1 = -INFINITY;
#pragma unroll
        for (int nt = 0; nt < 4; nt++) {
            rmax0 = fmaxf(rmax0, fmaxf(S[nt][0], S[nt][1]));
            rmax1 = fmaxf(rmax1, fmaxf(S[nt][2], S[nt][3]));
        }
        rmax0 = fmaxf(rmax0, __shfl_xor_sync(FM, rmax0, 1));
        rmax0 = fmaxf(rmax0, __shfl_xor_sync(FM, rmax0, 2));
        rmax1 = fmaxf(rmax1, __shfl_xor_sync(FM, rmax1, 1));
        rmax1 = fmaxf(rmax1, __shfl_xor_sync(FM, rmax1, 2));
        PMX[ch * 128 + r0] = rmax0;
        PMX[ch * 128 + r1] = rmax1;
        __syncthreads();   // C: pmax visible

        const float rfull0 = fmaxf(PMX[r0], PMX[128 + r0]);
        const float rfull1 = fmaxf(PMX[r1], PMX[128 + r1]);
        const float mn0 = fmaxf(m0, rfull0);
        const float mn1 = fmaxf(m1, rfull1);
        const float fr0 = exp2f((m0 - mn0) * L2E);
        const float fr1 = exp2f((m1 - mn1) * L2E);
        // liveness (uniform across each quad's 4 tig lanes)
        const bool live0 = (rmax0 - mn0) > DEAD;
        const bool live1 = (rmax1 - mn1) > DEAD;
        const bool livef0 = (rfull0 - mn0) > DEAD;
        const bool livef1 = (rfull1 - mn1) > DEAD;

        float rs0 = 0.f, rs1 = 0.f;
        if (live0) {
            const uint32_t mk = hash8_scatter(cbase0 + (uint32_t)t * 64u);
#pragma unroll
            for (int nt = 0; nt < 4; nt++) {
                float e00 = exp2f((S[nt][0] - mn0) * L2E);
                float e01 = exp2f((S[nt][1] - mn0) * L2E);
                rs0 += e00 + e01;
                float d00 = ((mk >> (nt * 2)) & 1u) ? e00 : 0.f;
                float d01 = ((mk >> (nt * 2 + 1)) & 1u) ? e01 : 0.f;
                PP[r0 * PPSTR + ch * 16 + nt * 4 + tig] = packh2(d00, d01);
            }
        } else {
#pragma unroll
            for (int nt = 0; nt < 4; nt++)
                PP[r0 * PPSTR + ch * 16 + nt * 4 + tig] = 0u;
        }
        if (live1) {
            const uint32_t mk = hash8_scatter(cbase1 + (uint32_t)t * 64u);
#pragma unroll
            for (int nt = 0; nt < 4; nt++) {
                float e10 = exp2f((S[nt][2] - mn1) * L2E);
                float e11 = exp2f((S[nt][3] - mn1) * L2E);
                rs1 += e10 + e11;
                float d10 = ((mk >> (nt * 2)) & 1u) ? e10 : 0.f;
                float d11 = ((mk >> (nt * 2 + 1)) & 1u) ? e11 : 0.f;
                PP[r1 * PPSTR + ch * 16 + nt * 4 + tig] = packh2(d10, d11);
            }
        } else {
#pragma unroll
            for (int nt = 0; nt < 4; nt++)
                PP[r1 * PPSTR + ch * 16 + nt * 4 + tig] = 0u;
        }
        rs0 += __shfl_xor_sync(FM, rs0, 1);
        rs0 += __shfl_xor_sync(FM, rs0, 2);
        rs1 += __shfl_xor_sync(FM, rs1, 1);
        rs1 += __shfl_xor_sync(FM, rs1, 2);
        PSM[ch * 128 + r0] = rs0;
        PSM[ch * 128 + r1] = rs1;

        // per-warp gemm2 skip vote (if skipped, all fr == 1 provably)
        const bool skip2 = __all_sync(FM, !(livef0 || livef1));

        CP_WAIT(1);        // V(t) ready (pending {K(t+1)})
        // D: barrier + block-wide vote (replaces plain __syncthreads)
        const int allskip = __syncthreads_and((int)(!(livef0 || livef1)));

        l0 = l0 * fr0 + PSM[r0] + PSM[128 + r0];
        l1 = l1 * fr1 + PSM[r1] + PSM[128 + r1];
        m0 = mn0; m1 = mn1;

        if (!allskip) {
            // ---- pack V raw -> VP[keypair][d] ----
            const int kp = tid >> 4;
            const int d0 = (tid & 15) * 8;
#pragma unroll
            for (int h = 0; h < 2; h++) {
                const int dd = d0 + h * 4;
                float4 a = *(const float4*)(VRAW + (2 * kp) * VRSTR + dd);
                float4 c2 = *(const float4*)(VRAW + (2 * kp + 1) * VRSTR + dd);
                uint4 o;
                o.x = packh2(a.x, c2.x);
                o.y = packh2(a.y, c2.y);
                o.z = packh2(a.z, c2.z);
                o.w = packh2(a.w, c2.w);
                *(uint4*)(VP + kp * VPSTR + dd) = o;
            }
            __syncthreads();   // E: VP visible; VRAW free
        }

        // ---- prefetch raw V(t+1) (VRAW unread past this point either way) ----
        if (t + 1 < NITER) {
            const float* vt = vb + (size_t)(t + 1) * BK * DD;
#pragma unroll
            for (int i = 0; i < 4; i++) {
                int row = ldrow + i * 16;
                cp16(sbVR + (uint32_t)(row * VRSTR + ldc4) * 4u, vt + row * DD + ldc4);
            }
        }
        CP_COMMIT();       // pending {K(t+1), V(t+1)}

        if (!skip2) {
            // rescale O, then gemm2
#pragma unroll
            for (int nt = 0; nt < 8; nt++) {
                O[nt][0] *= fr0; O[nt][1] *= fr0;
                O[nt][2] *= fr1; O[nt][3] *= fr1;
            }
#pragma unroll 1
            for (int ks = 0; ks < 4; ks++) {
                const int wp = ks * 8 + tig;
                uint32_t pa[4];
                pa[0] = PP[r0 * PPSTR + wp];
                pa[1] = PP[r1 * PPSTR + wp];
                pa[2] = PP[r0 * PPSTR + wp + 4];
                pa[3] = PP[r1 * PPSTR + wp + 4];
#pragma unroll
                for (int nt = 0; nt < 8; nt++) {
                    const int col = ch * 64 + nt * 8 + g;
                    uint32_t vb0 = VP[wp * VPSTR + col];
                    uint32_t vb1 = VP[(wp + 4) * VPSTR + col];
                    mma_f16(O[nt], pa, vb0, vb1);
                }
            }
        }
    }

    // ---- epilogue ----
    const float inv0 = 1.f / (l0 * 0.7f);
    const float inv1 = 1.f / (l1 * 0.7f);
    float* o0 = out + ((size_t)b * SS + gi0) * DD + ch * 64;
    float* o1 = out + ((size_t)b * SS + gi1) * DD + ch * 64;
#pragma unroll
    for (int nt = 0; nt < 8; nt++) {
        const int c = nt * 8 + 2 * tig;
        *(float2*)(o0 + c) = make_float2(O[nt][0] * inv0, O[nt][1] * inv0);
        *(float2*)(o1 + c) = make_float2(O[nt][2] * inv1, O[nt][3] * inv1);
    }
}

// ---------------------------------------------------------------------------
extern "C" void kernel_launch(void* const* d_in, const int* in_sizes, int n_in,
                              void* d_out, int out_size) {
    (void)in_sizes; (void)n_in; (void)out_size;
    const float* q = (const float*)d_in[0];
    const float* k = (const float*)d_in[1];
    const float* v = (const float*)d_in[2];
    const float* scale = (const float*)d_in[3];
    float* out = (float*)d_out;

    static const bool _init = []() {
        cudaFuncSetAttribute(attn_mma,
                             cudaFuncAttributeMaxDynamicSharedMemorySize,
                             SMEM_BYTES);
        return true;
    }();
    (void)_init;

    dim3 grid(SS / BQ, BB);
    attn_mma<<<grid, NTH, SMEM_BYTES>>>(q, k, v, scale, out);
}